// round 5
// baseline (speedup 1.0000x reference)
#include <cuda_runtime.h>

#define Gnum 1000
#define NPG  200
#define NN   200000
#define KNB  5
#define M    128
#define KC   32     // GEMM k-chunk held in shared memory
#define SPAD 132    // padded row stride for transposed s chunk (bank spread)

// Scratch (no allocation allowed): neighbor lists + ping-pong feature buffers.
// Referenced DIRECTLY from device code — kernel_launch does no symbol lookups.
__device__ int   g_nbr[NN * KNB];
__device__ float g_bufA[(size_t)NN * M];
__device__ float g_bufB[(size_t)NN * M];

// ---------------------------------------------------------------------------
// KNN: one block per graph. 200x200 distances, top-5 per node via unrolled
// insertion (static register indexing only -> no local-memory spill).
// Strict '<' keeps lowest-index-first on ties (matches top_k semantics).
// ---------------------------------------------------------------------------
__global__ void knn_kernel(const float* __restrict__ pos) {
    __shared__ float px[NPG], py[NPG], pz[NPG];
    int g = blockIdx.x;
    int t = threadIdx.x;
    if (t < NPG) {
        const float* p = pos + (size_t)(g * NPG + t) * 3;
        px[t] = p[0]; py[t] = p[1]; pz[t] = p[2];
    }
    __syncthreads();
    if (t >= NPG) return;

    float bd0 = 3.4e38f, bd1 = 3.4e38f, bd2 = 3.4e38f, bd3 = 3.4e38f, bd4 = 3.4e38f;
    int   bi0 = 0, bi1 = 0, bi2 = 0, bi3 = 0, bi4 = 0;
    float x0 = px[t], y0 = py[t], z0 = pz[t];

    for (int j = 0; j < NPG; j++) {
        if (j == t) continue;
        float dx = __fadd_rn(x0, -px[j]);
        float dy = __fadd_rn(y0, -py[j]);
        float dz = __fadd_rn(z0, -pz[j]);
        // no fma contraction: keep bit-compatible ordering for near-ties
        float d2 = __fadd_rn(__fadd_rn(__fmul_rn(dx, dx), __fmul_rn(dy, dy)),
                             __fmul_rn(dz, dz));
        if (d2 < bd4) {
            if (d2 < bd3) { bd4 = bd3; bi4 = bi3;
                if (d2 < bd2) { bd3 = bd2; bi3 = bi2;
                    if (d2 < bd1) { bd2 = bd1; bi2 = bi1;
                        if (d2 < bd0) { bd1 = bd0; bi1 = bi0; bd0 = d2; bi0 = j; }
                        else         { bd1 = d2; bi1 = j; }
                    } else { bd2 = d2; bi2 = j; }
                } else { bd3 = d2; bi3 = j; }
            } else { bd4 = d2; bi4 = j; }
        }
    }
    int base = (g * NPG + t) * KNB;
    int off  = g * NPG;
    g_nbr[base + 0] = off + bi0;
    g_nbr[base + 1] = off + bi1;
    g_nbr[base + 2] = off + bi2;
    g_nbr[base + 3] = off + bi3;
    g_nbr[base + 4] = off + bi4;
}

// ---------------------------------------------------------------------------
// Fused GCN layer. Degree is uniformly K+1=6 -> symmetric norm == 1/6 for
// every edge AND the self loop, so:
//   s[i] = (x[i] + sum_{j in knn(i)} x[j]) / 6
//   x'   = relu(s @ W + b)
// (aggregation commutes with the linear map, so we aggregate FIRST, then do
// one GEMM -- no per-edge GEMM-output gather/scatter, no atomics.)
//
// Block = 128 rows x 128 cols, 256 threads, 8x8 register microtiles.
// k-loop chunked by KC=32 so static shared stays < 48 KB (no attribute call,
// occupancy 2 blocks/SM).
// mode: 0 = emb[z] -> bufA, 1 = bufA -> bufB, 2 = bufB -> bufA.
// ---------------------------------------------------------------------------
__global__ void __launch_bounds__(256, 2) gcn_layer_kernel(
    const int*   __restrict__ z,
    const float* __restrict__ emb,
    const float* __restrict__ W,
    const float* __restrict__ bias,
    int mode)
{
    __shared__ float Wsm[KC][M];     // 16 KB
    __shared__ float sT [KC][SPAD];  // 16.9 KB, [k][row] transposed agg chunk

    const float* xin  = (mode == 1) ? g_bufA : g_bufB;
    float*       xout = (mode == 1) ? g_bufB : g_bufA;

    int t     = threadIdx.x;
    int tile0 = blockIdx.x * 128;

    // Per-thread gather assignment: row r, k-half (16 k's per chunk-half).
    int r    = t >> 1;
    int half = t & 1;
    int i    = tile0 + r;
    bool valid = (i < NN);

    const float* rows[6];
    if (valid) {
        if (mode == 0) {
            rows[0] = emb + (size_t)z[i] * M;
            #pragma unroll
            for (int j = 0; j < KNB; j++)
                rows[1 + j] = emb + (size_t)z[g_nbr[i * KNB + j]] * M;
        } else {
            rows[0] = xin + (size_t)i * M;
            #pragma unroll
            for (int j = 0; j < KNB; j++)
                rows[1 + j] = xin + (size_t)g_nbr[i * KNB + j] * M;
        }
    }

    int tr = t >> 4, tc = t & 15;
    int r0 = tr * 8, c0 = tc * 8;
    float acc[8][8];
    #pragma unroll
    for (int a = 0; a < 8; a++)
        #pragma unroll
        for (int b = 0; b < 8; b++) acc[a][b] = 0.f;

    const float wnorm = 1.0f / 6.0f;

    for (int chunk = 0; chunk < M / KC; chunk++) {
        int kc0 = chunk * KC;
        __syncthreads();   // previous chunk's compute done before overwrite

        // Stage W chunk: KC*M floats = 1024 float4, 256 threads -> 4 each
        {
            const float4* Wg = (const float4*)(W + (size_t)kc0 * M);
            float4* Ws = (float4*)&Wsm[0][0];
            #pragma unroll
            for (int u = 0; u < KC * M / 4 / 256; u++)
                Ws[t + u * 256] = Wg[t + u * 256];
        }

        // Build transposed aggregated chunk: this thread covers 16 k's of row r
        {
            int kb = half * (KC / 2);   // local k base within chunk
            if (valid) {
                #pragma unroll
                for (int kk = 0; kk < KC / 2; kk += 4) {
                    int kl = kb + kk;          // local k
                    int kg = kc0 + kl;         // global k
                    float4 a = *(const float4*)(rows[0] + kg);
                    #pragma unroll
                    for (int j = 1; j < 6; j++) {
                        float4 u = *(const float4*)(rows[j] + kg);
                        a.x += u.x; a.y += u.y; a.z += u.z; a.w += u.w;
                    }
                    sT[kl + 0][r] = a.x * wnorm;
                    sT[kl + 1][r] = a.y * wnorm;
                    sT[kl + 2][r] = a.z * wnorm;
                    sT[kl + 3][r] = a.w * wnorm;
                }
            } else {
                #pragma unroll
                for (int kk = 0; kk < KC / 2; kk++) sT[kb + kk][r] = 0.f;
            }
        }
        __syncthreads();

        // Accumulate this k-chunk: 8x8 microtile
        #pragma unroll
        for (int k = 0; k < KC; k++) {
            float4 a0 = *(const float4*)&sT[k][r0];
            float4 a1 = *(const float4*)&sT[k][r0 + 4];
            float4 b0 = *(const float4*)&Wsm[k][c0];
            float4 b1 = *(const float4*)&Wsm[k][c0 + 4];
            float av[8] = {a0.x, a0.y, a0.z, a0.w, a1.x, a1.y, a1.z, a1.w};
            float bv[8] = {b0.x, b0.y, b0.z, b0.w, b1.x, b1.y, b1.z, b1.w};
            #pragma unroll
            for (int a = 0; a < 8; a++)
                #pragma unroll
                for (int b = 0; b < 8; b++)
                    acc[a][b] = fmaf(av[a], bv[b], acc[a][b]);
        }
    }

    // Epilogue: + bias, relu, vectorized store
    float bb[8];
    #pragma unroll
    for (int b = 0; b < 8; b++) bb[b] = bias[c0 + b];
    #pragma unroll
    for (int a = 0; a < 8; a++) {
        int row = tile0 + r0 + a;
        if (row < NN) {
            float4 o0, o1;
            o0.x = fmaxf(acc[a][0] + bb[0], 0.f);
            o0.y = fmaxf(acc[a][1] + bb[1], 0.f);
            o0.z = fmaxf(acc[a][2] + bb[2], 0.f);
            o0.w = fmaxf(acc[a][3] + bb[3], 0.f);
            o1.x = fmaxf(acc[a][4] + bb[4], 0.f);
            o1.y = fmaxf(acc[a][5] + bb[5], 0.f);
            o1.z = fmaxf(acc[a][6] + bb[6], 0.f);
            o1.w = fmaxf(acc[a][7] + bb[7], 0.f);
            *(float4*)&xout[(size_t)row * M + c0]     = o0;
            *(float4*)&xout[(size_t)row * M + c0 + 4] = o1;
        }
    }
}

// ---------------------------------------------------------------------------
// Fused mean-pool + 3-layer MLP regressor. One block (128 threads) per graph.
// Final features live in g_bufA (after layer 2, mode=2).
// ---------------------------------------------------------------------------
__global__ void pool_mlp_kernel(
    const float* __restrict__ rW1, const float* __restrict__ rb1,
    const float* __restrict__ rW2, const float* __restrict__ rb2,
    const float* __restrict__ rW3, const float* __restrict__ rb3,
    float* __restrict__ out)
{
    __shared__ float p[M];
    __shared__ float h1[64];
    __shared__ float h2[32];
    int g = blockIdx.x, t = threadIdx.x;

    const float* base = g_bufA + (size_t)g * NPG * M;
    float s = 0.f;
    for (int i = 0; i < NPG; i++) s += base[(size_t)i * M + t];
    p[t] = s / (float)NPG;
    __syncthreads();

    if (t < 64) {
        float a = rb1[t];
        for (int k = 0; k < M; k++) a = fmaf(p[k], rW1[k * 64 + t], a);
        h1[t] = fmaxf(a, 0.f);
    }
    __syncthreads();
    if (t < 32) {
        float a = rb2[t];
        for (int k = 0; k < 64; k++) a = fmaf(h1[k], rW2[k * 32 + t], a);
        h2[t] = fmaxf(a, 0.f);
    }
    __syncthreads();
    if (t < 32) {
        float a = h2[t] * rW3[t];
        #pragma unroll
        for (int off = 16; off; off >>= 1) a += __shfl_down_sync(0xffffffffu, a, off);
        if (t == 0) out[g] = a + rb3[0];
    }
}

// ---------------------------------------------------------------------------
// kernel_launch: ONLY kernel launches — no symbol lookups, no attribute
// calls, nothing for graph capture or the allocation guards to trip on.
// ---------------------------------------------------------------------------
extern "C" void kernel_launch(void* const* d_in, const int* in_sizes, int n_in,
                              void* d_out, int out_size)
{
    const int*   z     = (const int*)  d_in[0];
    const float* pos   = (const float*)d_in[1];
    // d_in[2] = batch (uniform: node i -> graph i/200) — unused
    const float* emb   = (const float*)d_in[3];
    const float* convW = (const float*)d_in[4];
    const float* convb = (const float*)d_in[5];
    const float* rW1   = (const float*)d_in[6];
    const float* rb1   = (const float*)d_in[7];
    const float* rW2   = (const float*)d_in[8];
    const float* rb2   = (const float*)d_in[9];
    const float* rW3   = (const float*)d_in[10];
    const float* rb3   = (const float*)d_in[11];
    float* out = (float*)d_out;

    knn_kernel<<<Gnum, 256>>>(pos);

    int ntiles = (NN + 127) / 128;
    gcn_layer_kernel<<<ntiles, 256>>>(z, emb, convW + 0 * M * M, convb + 0 * M, 0);
    gcn_layer_kernel<<<ntiles, 256>>>(z, emb, convW + 1 * M * M, convb + 1 * M, 1);
    gcn_layer_kernel<<<ntiles, 256>>>(z, emb, convW + 2 * M * M, convb + 2 * M, 2);

    pool_mlp_kernel<<<Gnum, 128>>>(rW1, rb1, rW2, rb2, rW3, rb3, out);
}

// round 6
// speedup vs baseline: 1.4272x; 1.4272x over previous
#include <cuda_runtime.h>

#define Gnum 1000
#define NPG  200
#define NN   200000
#define KNB  5
#define M    128
#define KCH  16     // K chunk per smem stage (2 mma k-steps)
#define AS   20     // sA row stride (floats): bank = (4g+tg) -> conflict-free
#define WS   136    // W row stride (floats): bank = (8tg+g) -> conflict-free

// Scratch (no allocation allowed): neighbor lists + ping-pong feature buffers.
__device__ int   g_nbr[NN * KNB];
__device__ float g_bufA[(size_t)NN * M];
__device__ float g_bufB[(size_t)NN * M];

// ---------------------------------------------------------------------------
// tf32 helpers: cvt.rna.tf32.f32 yields an f32 bit-pattern with the low 13
// mantissa bits cleared (round-to-nearest) -> reinterpretable as float.
// ---------------------------------------------------------------------------
__device__ __forceinline__ float f2tf(float x) {
    unsigned r;
    asm("cvt.rna.tf32.f32 %0, %1;" : "=r"(r) : "f"(x));
    return __uint_as_float(r);
}

#define MMA_TF32(d, a, b)                                                     \
    asm volatile(                                                             \
        "mma.sync.aligned.m16n8k8.row.col.f32.tf32.tf32.f32 "                 \
        "{%0,%1,%2,%3},{%4,%5,%6,%7},{%8,%9},{%0,%1,%2,%3};"                  \
        : "+f"(d[0]), "+f"(d[1]), "+f"(d[2]), "+f"(d[3])                      \
        : "r"(a[0]), "r"(a[1]), "r"(a[2]), "r"(a[3]), "r"(b[0]), "r"(b[1]))

// ---------------------------------------------------------------------------
// KNN: one block per graph (unchanged from passing R5 kernel).
// ---------------------------------------------------------------------------
__global__ void knn_kernel(const float* __restrict__ pos) {
    __shared__ float px[NPG], py[NPG], pz[NPG];
    int g = blockIdx.x;
    int t = threadIdx.x;
    if (t < NPG) {
        const float* p = pos + (size_t)(g * NPG + t) * 3;
        px[t] = p[0]; py[t] = p[1]; pz[t] = p[2];
    }
    __syncthreads();
    if (t >= NPG) return;

    float bd0 = 3.4e38f, bd1 = 3.4e38f, bd2 = 3.4e38f, bd3 = 3.4e38f, bd4 = 3.4e38f;
    int   bi0 = 0, bi1 = 0, bi2 = 0, bi3 = 0, bi4 = 0;
    float x0 = px[t], y0 = py[t], z0 = pz[t];

    for (int j = 0; j < NPG; j++) {
        if (j == t) continue;
        float dx = __fadd_rn(x0, -px[j]);
        float dy = __fadd_rn(y0, -py[j]);
        float dz = __fadd_rn(z0, -pz[j]);
        float d2 = __fadd_rn(__fadd_rn(__fmul_rn(dx, dx), __fmul_rn(dy, dy)),
                             __fmul_rn(dz, dz));
        if (d2 < bd4) {
            if (d2 < bd3) { bd4 = bd3; bi4 = bi3;
                if (d2 < bd2) { bd3 = bd2; bi3 = bi2;
                    if (d2 < bd1) { bd2 = bd1; bi2 = bi1;
                        if (d2 < bd0) { bd1 = bd0; bi1 = bi0; bd0 = d2; bi0 = j; }
                        else         { bd1 = d2; bi1 = j; }
                    } else { bd2 = d2; bi2 = j; }
                } else { bd3 = d2; bi3 = j; }
            } else { bd4 = d2; bi4 = j; }
        }
    }
    int base = (g * NPG + t) * KNB;
    int off  = g * NPG;
    g_nbr[base + 0] = off + bi0;
    g_nbr[base + 1] = off + bi1;
    g_nbr[base + 2] = off + bi2;
    g_nbr[base + 3] = off + bi3;
    g_nbr[base + 4] = off + bi4;
}

// ---------------------------------------------------------------------------
// Gather 8 aggregated floats for one row at global k-offset kg:
//   s[r][kg..kg+7] = (x[r] + sum of 5 knn rows)[kg..kg+7] / 6
// ---------------------------------------------------------------------------
__device__ __forceinline__ void gather8(const float* __restrict__ base,
                                        const unsigned* offs, bool v, int kg,
                                        float4& a0, float4& a1) {
    a0 = make_float4(0.f, 0.f, 0.f, 0.f);
    a1 = make_float4(0.f, 0.f, 0.f, 0.f);
    if (v) {
        const float* p = base + offs[0] + kg;
        a0 = *(const float4*)p;
        a1 = *(const float4*)(p + 4);
        #pragma unroll
        for (int j = 1; j < 6; j++) {
            const float* q = base + offs[j] + kg;
            float4 u0 = *(const float4*)q;
            float4 u1 = *(const float4*)(q + 4);
            a0.x += u0.x; a0.y += u0.y; a0.z += u0.z; a0.w += u0.w;
            a1.x += u1.x; a1.y += u1.y; a1.z += u1.z; a1.w += u1.w;
        }
        const float w = 1.0f / 6.0f;
        a0.x *= w; a0.y *= w; a0.z *= w; a0.w *= w;
        a1.x *= w; a1.y *= w; a1.z *= w; a1.w *= w;
    }
}

// ---------------------------------------------------------------------------
// Fused GCN layer, tensor-core edition.
//   s[i] = (x[i] + sum_knn x[j]) / 6  (uniform degree 6 -> norm == 1/6)
//   x'   = relu(s @ W + b),  s in tf32, W split hi+lo tf32 (compensated).
// Block: 128 rows x 128 cols, 8 warps as 2(m) x 4(n), warp = 64x32,
// mma m16n8k8, fp32 accum. K chunked by 16, gather prefetched under MMA.
// mode: 0 = emb[z] -> bufA, 1 = bufA -> bufB, 2 = bufB -> bufA.
// ---------------------------------------------------------------------------
__global__ void __launch_bounds__(256, 2) gcn_layer_kernel(
    const int*   __restrict__ z,
    const float* __restrict__ emb,
    const float* __restrict__ W,
    const float* __restrict__ bias,
    int mode)
{
    __shared__ float sA [128][AS];   // 10.2 KB aggregated rows (tf32-rounded)
    __shared__ float sWh[KCH][WS];   //  8.5 KB W chunk, tf32 hi
    __shared__ float sWl[KCH][WS];   //  8.5 KB W chunk, tf32 lo

    const float* xin  = (mode == 1) ? g_bufA : g_bufB;
    float*       xout = (mode == 1) ? g_bufB : g_bufA;

    int t     = threadIdx.x;
    int tile0 = blockIdx.x * 128;

    // --- gather assignment: 2 threads per row, 8 k's per chunk each ---
    int gr = t >> 1, gh = t & 1;
    int gi = tile0 + gr;
    bool gvalid = (gi < NN);
    const float* gbase = (mode == 0) ? emb : xin;
    unsigned offs[6] = {0, 0, 0, 0, 0, 0};
    if (gvalid) {
        if (mode == 0) {
            offs[0] = (unsigned)z[gi] * M;
            #pragma unroll
            for (int j = 0; j < KNB; j++)
                offs[1 + j] = (unsigned)z[g_nbr[gi * KNB + j]] * M;
        } else {
            offs[0] = (unsigned)gi * M;
            #pragma unroll
            for (int j = 0; j < KNB; j++)
                offs[1 + j] = (unsigned)g_nbr[gi * KNB + j] * M;
        }
    }

    // --- W staging assignment: thread -> (row t>>4, 8 cols) of the chunk ---
    int wr = t >> 4, wc = (t & 15) * 8;

    // --- mma assignment ---
    int lane = t & 31, wid = t >> 5;
    int g  = lane >> 2, tg = lane & 3;
    int wm0 = (wid >> 2) * 64;       // warp row base within tile
    int wn0 = (wid & 3) * 32;        // warp col base

    float acc[4][4][4];
    #pragma unroll
    for (int mi = 0; mi < 4; mi++)
        #pragma unroll
        for (int ni = 0; ni < 4; ni++)
            #pragma unroll
            for (int q = 0; q < 4; q++) acc[mi][ni][q] = 0.f;

    // prefetch chunk 0 gather
    float4 pa0, pa1;
    gather8(gbase, offs, gvalid, gh * 8, pa0, pa1);

    for (int c = 0; c < M / KCH; c++) {
        // stage W chunk (L1-hot after the first block on each SM)
        {
            const float* wsrc = W + (size_t)(c * KCH + wr) * M + wc;
            float4 w0 = *(const float4*)wsrc;
            float4 w1 = *(const float4*)(wsrc + 4);
            float4 h0, h1, l0, l1;
            h0.x = f2tf(w0.x); l0.x = f2tf(w0.x - h0.x);
            h0.y = f2tf(w0.y); l0.y = f2tf(w0.y - h0.y);
            h0.z = f2tf(w0.z); l0.z = f2tf(w0.z - h0.z);
            h0.w = f2tf(w0.w); l0.w = f2tf(w0.w - h0.w);
            h1.x = f2tf(w1.x); l1.x = f2tf(w1.x - h1.x);
            h1.y = f2tf(w1.y); l1.y = f2tf(w1.y - h1.y);
            h1.z = f2tf(w1.z); l1.z = f2tf(w1.z - h1.z);
            h1.w = f2tf(w1.w); l1.w = f2tf(w1.w - h1.w);
            *(float4*)&sWh[wr][wc]     = h0;
            *(float4*)&sWh[wr][wc + 4] = h1;
            *(float4*)&sWl[wr][wc]     = l0;
            *(float4*)&sWl[wr][wc + 4] = l1;
        }
        // stage aggregated rows (tf32-rounded)
        {
            float4 s0, s1;
            s0.x = f2tf(pa0.x); s0.y = f2tf(pa0.y);
            s0.z = f2tf(pa0.z); s0.w = f2tf(pa0.w);
            s1.x = f2tf(pa1.x); s1.y = f2tf(pa1.y);
            s1.z = f2tf(pa1.z); s1.w = f2tf(pa1.w);
            *(float4*)&sA[gr][gh * 8]     = s0;
            *(float4*)&sA[gr][gh * 8 + 4] = s1;
        }
        __syncthreads();

        // prefetch next chunk's gather under the MMAs
        float4 na0 = make_float4(0.f, 0.f, 0.f, 0.f);
        float4 na1 = make_float4(0.f, 0.f, 0.f, 0.f);
        if (c < M / KCH - 1)
            gather8(gbase, offs, gvalid, (c + 1) * KCH + gh * 8, na0, na1);

        // MMA over this chunk: 2 k-steps of 8
        #pragma unroll
        for (int ks = 0; ks < 2; ks++) {
            int k0 = ks * 8;
            unsigned a[4][4];
            #pragma unroll
            for (int mi = 0; mi < 4; mi++) {
                int m0 = wm0 + mi * 16;
                a[mi][0] = __float_as_uint(sA[m0 + g][k0 + tg]);
                a[mi][1] = __float_as_uint(sA[m0 + g + 8][k0 + tg]);
                a[mi][2] = __float_as_uint(sA[m0 + g][k0 + tg + 4]);
                a[mi][3] = __float_as_uint(sA[m0 + g + 8][k0 + tg + 4]);
            }
            unsigned b[4][2];
            #pragma unroll
            for (int ni = 0; ni < 4; ni++) {
                int n0 = wn0 + ni * 8;
                b[ni][0] = __float_as_uint(sWh[k0 + tg][n0 + g]);
                b[ni][1] = __float_as_uint(sWh[k0 + tg + 4][n0 + g]);
            }
            #pragma unroll
            for (int mi = 0; mi < 4; mi++)
                #pragma unroll
                for (int ni = 0; ni < 4; ni++)
                    MMA_TF32(acc[mi][ni], a[mi], b[ni]);
            #pragma unroll
            for (int ni = 0; ni < 4; ni++) {
                int n0 = wn0 + ni * 8;
                b[ni][0] = __float_as_uint(sWl[k0 + tg][n0 + g]);
                b[ni][1] = __float_as_uint(sWl[k0 + tg + 4][n0 + g]);
            }
            #pragma unroll
            for (int mi = 0; mi < 4; mi++)
                #pragma unroll
                for (int ni = 0; ni < 4; ni++)
                    MMA_TF32(acc[mi][ni], a[mi], b[ni]);
        }
        __syncthreads();
        pa0 = na0; pa1 = na1;
    }

    // Epilogue: bias + relu, float2 stores (c-frag rows g and g+8, cols 2*tg,2*tg+1)
    #pragma unroll
    for (int ni = 0; ni < 4; ni++) {
        int cc = wn0 + ni * 8 + 2 * tg;
        float b0 = bias[cc], b1 = bias[cc + 1];
        #pragma unroll
        for (int mi = 0; mi < 4; mi++) {
            int r1 = tile0 + wm0 + mi * 16 + g;
            if (r1 < NN) {
                float2 o;
                o.x = fmaxf(acc[mi][ni][0] + b0, 0.f);
                o.y = fmaxf(acc[mi][ni][1] + b1, 0.f);
                *(float2*)&xout[(size_t)r1 * M + cc] = o;
            }
            int r2 = r1 + 8;
            if (r2 < NN) {
                float2 o;
                o.x = fmaxf(acc[mi][ni][2] + b0, 0.f);
                o.y = fmaxf(acc[mi][ni][3] + b1, 0.f);
                *(float2*)&xout[(size_t)r2 * M + cc] = o;
            }
        }
    }
}

// ---------------------------------------------------------------------------
// Fused mean-pool + 3-layer MLP regressor (reads g_bufA after layer 2).
// ---------------------------------------------------------------------------
__global__ void pool_mlp_kernel(
    const float* __restrict__ rW1, const float* __restrict__ rb1,
    const float* __restrict__ rW2, const float* __restrict__ rb2,
    const float* __restrict__ rW3, const float* __restrict__ rb3,
    float* __restrict__ out)
{
    __shared__ float p[M];
    __shared__ float h1[64];
    __shared__ float h2[32];
    int g = blockIdx.x, t = threadIdx.x;

    const float* base = g_bufA + (size_t)g * NPG * M;
    float s = 0.f;
    for (int i = 0; i < NPG; i++) s += base[(size_t)i * M + t];
    p[t] = s / (float)NPG;
    __syncthreads();

    if (t < 64) {
        float a = rb1[t];
        for (int k = 0; k < M; k++) a = fmaf(p[k], rW1[k * 64 + t], a);
        h1[t] = fmaxf(a, 0.f);
    }
    __syncthreads();
    if (t < 32) {
        float a = rb2[t];
        for (int k = 0; k < 64; k++) a = fmaf(h1[k], rW2[k * 32 + t], a);
        h2[t] = fmaxf(a, 0.f);
    }
    __syncthreads();
    if (t < 32) {
        float a = h2[t] * rW3[t];
        #pragma unroll
        for (int off = 16; off; off >>= 1) a += __shfl_down_sync(0xffffffffu, a, off);
        if (t == 0) out[g] = a + rb3[0];
    }
}

// ---------------------------------------------------------------------------
// kernel_launch: ONLY kernel launches (proven capture-safe path).
// ---------------------------------------------------------------------------
extern "C" void kernel_launch(void* const* d_in, const int* in_sizes, int n_in,
                              void* d_out, int out_size)
{
    const int*   z     = (const int*)  d_in[0];
    const float* pos   = (const float*)d_in[1];
    // d_in[2] = batch (uniform: node i -> graph i/200) — unused
    const float* emb   = (const float*)d_in[3];
    const float* convW = (const float*)d_in[4];
    const float* convb = (const float*)d_in[5];
    const float* rW1   = (const float*)d_in[6];
    const float* rb1   = (const float*)d_in[7];
    const float* rW2   = (const float*)d_in[8];
    const float* rb2   = (const float*)d_in[9];
    const float* rW3   = (const float*)d_in[10];
    const float* rb3   = (const float*)d_in[11];
    float* out = (float*)d_out;

    knn_kernel<<<Gnum, 256>>>(pos);

    int ntiles = (NN + 127) / 128;
    gcn_layer_kernel<<<ntiles, 256>>>(z, emb, convW + 0 * M * M, convb + 0 * M, 0);
    gcn_layer_kernel<<<ntiles, 256>>>(z, emb, convW + 1 * M * M, convb + 1 * M, 1);
    gcn_layer_kernel<<<ntiles, 256>>>(z, emb, convW + 2 * M * M, convb + 2 * M, 2);

    pool_mlp_kernel<<<Gnum, 128>>>(rW1, rb1, rW2, rb2, rW3, rb3, out);
}

// round 7
// speedup vs baseline: 1.4806x; 1.0374x over previous
#include <cuda_runtime.h>

#define Gnum 1000
#define NPG  200
#define NN   200000
#define KNB  5
#define M    128
#define CH   32       // K per smem stage (4 mma k-steps)
#define NCHK (M / CH) // 4 chunks

// Scratch (no allocation allowed): neighbor lists + ping-pong feature buffers.
__device__ int   g_nbr[NN * KNB];
__device__ float g_bufA[(size_t)NN * M];
__device__ float g_bufB[(size_t)NN * M];

// ---------------------------------------------------------------------------
// tf32 helpers
// ---------------------------------------------------------------------------
__device__ __forceinline__ float f2tf(float x) {
    unsigned r;
    asm("cvt.rna.tf32.f32 %0, %1;" : "=r"(r) : "f"(x));
    return __uint_as_float(r);
}

#define MMA_TF32(d, a, b0, b1)                                                \
    asm volatile(                                                             \
        "mma.sync.aligned.m16n8k8.row.col.f32.tf32.tf32.f32 "                 \
        "{%0,%1,%2,%3},{%4,%5,%6,%7},{%8,%9},{%0,%1,%2,%3};"                  \
        : "+f"(d[0]), "+f"(d[1]), "+f"(d[2]), "+f"(d[3])                      \
        : "r"(a.x), "r"(a.y), "r"(a.z), "r"(a.w), "r"(b0), "r"(b1))

// ---------------------------------------------------------------------------
// KNN: one block per graph (unchanged — proven correct).
// ---------------------------------------------------------------------------
__global__ void knn_kernel(const float* __restrict__ pos) {
    __shared__ float px[NPG], py[NPG], pz[NPG];
    int g = blockIdx.x;
    int t = threadIdx.x;
    if (t < NPG) {
        const float* p = pos + (size_t)(g * NPG + t) * 3;
        px[t] = p[0]; py[t] = p[1]; pz[t] = p[2];
    }
    __syncthreads();
    if (t >= NPG) return;

    float bd0 = 3.4e38f, bd1 = 3.4e38f, bd2 = 3.4e38f, bd3 = 3.4e38f, bd4 = 3.4e38f;
    int   bi0 = 0, bi1 = 0, bi2 = 0, bi3 = 0, bi4 = 0;
    float x0 = px[t], y0 = py[t], z0 = pz[t];

    for (int j = 0; j < NPG; j++) {
        if (j == t) continue;
        float dx = __fadd_rn(x0, -px[j]);
        float dy = __fadd_rn(y0, -py[j]);
        float dz = __fadd_rn(z0, -pz[j]);
        float d2 = __fadd_rn(__fadd_rn(__fmul_rn(dx, dx), __fmul_rn(dy, dy)),
                             __fmul_rn(dz, dz));
        if (d2 < bd4) {
            if (d2 < bd3) { bd4 = bd3; bi4 = bi3;
                if (d2 < bd2) { bd3 = bd2; bi3 = bi2;
                    if (d2 < bd1) { bd2 = bd1; bi2 = bi1;
                        if (d2 < bd0) { bd1 = bd0; bi1 = bi0; bd0 = d2; bi0 = j; }
                        else         { bd1 = d2; bi1 = j; }
                    } else { bd2 = d2; bi2 = j; }
                } else { bd3 = d2; bi3 = j; }
            } else { bd4 = d2; bi4 = j; }
        }
    }
    int base = (g * NPG + t) * KNB;
    int off  = g * NPG;
    g_nbr[base + 0] = off + bi0;
    g_nbr[base + 1] = off + bi1;
    g_nbr[base + 2] = off + bi2;
    g_nbr[base + 3] = off + bi3;
    g_nbr[base + 4] = off + bi4;
}

// ---------------------------------------------------------------------------
// Fused GCN layer, tensor-core + fragment-layout smem edition.
//   s[i] = (x[i] + sum_knn x[j]) / 6 ;  x' = relu(s @ W + b)
//   s in tf32, W split hi+lo tf32 (compensated), fp32 accum.
//
// Block: 128 rows x 128 cols, 8 warps = 2(m-half) x 4(n), warp 64x32,
// mma m16n8k8. K chunked by 32.
//  - Gather: 8 threads/row (16B each) -> warp-wide LDG touches only 4 lines.
//  - A chunk stored DIRECTLY in mma fragment layout -> 1 LDS.128 per a-frag.
//  - W chunk packed float4 {hi(k),hi(k+4),lo(k),lo(k+4)} with XOR(2*tg)
//    swizzle -> 1 conflict-free LDS.128 yields both hi and lo b-frags.
// mode: 0 = emb[z] -> bufA, 1 = bufA -> bufB, 2 = bufB -> bufA.
// ---------------------------------------------------------------------------
__global__ void __launch_bounds__(256, 2) gcn_layer_kernel(
    const int*   __restrict__ z,
    const float* __restrict__ emb,
    const float* __restrict__ W,
    const float* __restrict__ bias,
    int mode)
{
    // A frag chunk: [h][ks][mi][g][tg] float4-slots, slot = pos_row + 2*pos_hi
    __shared__ float  sAf[2 * 4 * 4 * 8 * 4 * 4];   // 16384 B
    // W packed chunk: [ks][tg][n^ (2*tg)] float4 {hi_k, hi_k4, lo_k, lo_k4}
    __shared__ float4 sWf[4 * 4 * 128];             // 32768 B   (total 48 KB)

    const float* xin  = (mode == 1) ? g_bufA : g_bufB;
    float*       xout = (mode == 1) ? g_bufB : g_bufA;
    const float* gbase = (mode == 0) ? emb : xin;

    int t     = threadIdx.x;
    int tile0 = blockIdx.x * 128;

    // ---- gather role: thread owns 16B (4 floats) of one row per pass ----
    int sub   = t & 7;        // which 16B segment of the 128B chunk-row
    int rbase = t >> 3;       // 0..31, row within pass
    int ksg   = sub >> 1;     // ks of my 4 floats
    int poshi = sub & 1;      // tg+4 half?

    unsigned offs[4][6];
    bool val[4];
    #pragma unroll
    for (int p = 0; p < 4; p++) {
        int r = p * 32 + rbase;
        int i = tile0 + r;
        val[p] = (i < NN);
        if (val[p]) {
            if (mode == 0) {
                offs[p][0] = (unsigned)z[i] * M;
                #pragma unroll
                for (int j = 0; j < KNB; j++)
                    offs[p][1 + j] = (unsigned)z[g_nbr[i * KNB + j]] * M;
            } else {
                offs[p][0] = (unsigned)i * M;
                #pragma unroll
                for (int j = 0; j < KNB; j++)
                    offs[p][1 + j] = (unsigned)g_nbr[i * KNB + j] * M;
            }
        } else {
            #pragma unroll
            for (int j = 0; j < 6; j++) offs[p][j] = 0;
        }
    }

    // ---- W staging role: thread -> (wks, wtg, 8 consecutive n) ----
    int wks = t >> 6;            // 0..3
    int wtg = (t >> 4) & 3;      // 0..3
    int wn  = (t & 15) * 8;      // 0..120

    // ---- mma role ----
    int lane = t & 31, wid = t >> 5;
    int g  = lane >> 2, tg = lane & 3;
    int h  = wid >> 2;                 // m-half (rows h*64 ..)
    int wn0 = (wid & 3) * 32;          // warp col base

    float acc[4][4][4];
    #pragma unroll
    for (int mi = 0; mi < 4; mi++)
        #pragma unroll
        for (int ni = 0; ni < 4; ni++)
            #pragma unroll
            for (int q = 0; q < 4; q++) acc[mi][ni][q] = 0.f;

    for (int c = 0; c < NCHK; c++) {
        if (c) __syncthreads();

        // ---- stage W chunk: 4 coalesced LDG.128, convert, 8 STS.128 ----
        {
            const float* w0 = W + (size_t)(c * CH + wks * 8 + wtg) * M + wn;
            const float* w1 = w0 + 4 * M;
            float4 A0 = *(const float4*)w0;
            float4 A1 = *(const float4*)(w0 + 4);
            float4 B0 = *(const float4*)w1;
            float4 B1 = *(const float4*)(w1 + 4);
            float wa[8] = {A0.x, A0.y, A0.z, A0.w, A1.x, A1.y, A1.z, A1.w};
            float wb[8] = {B0.x, B0.y, B0.z, B0.w, B1.x, B1.y, B1.z, B1.w};
            float4* dstrow = &sWf[(wks * 4 + wtg) * 128];
            int xr = 2 * wtg;
            #pragma unroll
            for (int i2 = 0; i2 < 8; i2++) {
                float ha = f2tf(wa[i2]);
                float la = f2tf(wa[i2] - ha);
                float hb = f2tf(wb[i2]);
                float lb = f2tf(wb[i2] - hb);
                dstrow[(wn + i2) ^ xr] = make_float4(ha, hb, la, lb);
            }
        }

        // ---- gather + scatter into A fragment layout ----
        #pragma unroll
        for (int p = 0; p < 4; p++) {
            int r = p * 32 + rbase;
            float v0 = 0.f, v1 = 0.f, v2 = 0.f, v3 = 0.f;
            if (val[p]) {
                int kg = c * CH + sub * 4;
                const float* pr = gbase + offs[p][0] + kg;
                float4 a = *(const float4*)pr;
                #pragma unroll
                for (int j = 1; j < 6; j++) {
                    float4 u = *(const float4*)(gbase + offs[p][j] + kg);
                    a.x += u.x; a.y += u.y; a.z += u.z; a.w += u.w;
                }
                const float wnm = 1.0f / 6.0f;
                v0 = f2tf(a.x * wnm); v1 = f2tf(a.y * wnm);
                v2 = f2tf(a.z * wnm); v3 = f2tf(a.w * wnm);
            }
            int hh = r >> 6, mi = (r >> 4) & 3, gg = r & 7, posr = (r >> 3) & 1;
            int s = posr + 2 * poshi;
            int fb = ((((hh * 4 + ksg) * 4 + mi) * 8 + gg) * 4) * 4 + s;
            sAf[fb +  0] = v0;
            sAf[fb +  4] = v1;
            sAf[fb +  8] = v2;
            sAf[fb + 12] = v3;
        }
        __syncthreads();

        // ---- MMA over chunk: 4 k-steps ----
        #pragma unroll
        for (int ks = 0; ks < 4; ks++) {
            uint4 a4[4];
            #pragma unroll
            for (int mi = 0; mi < 4; mi++) {
                int fidx = (((h * 4 + ks) * 4 + mi) * 8 + g) * 4 + tg;
                a4[mi] = *(const uint4*)&sAf[fidx * 4];
            }
            float4 b4[4];
            #pragma unroll
            for (int ni = 0; ni < 4; ni++) {
                int n = wn0 + ni * 8 + g;
                b4[ni] = sWf[(ks * 4 + tg) * 128 + (n ^ (2 * tg))];
            }
            #pragma unroll
            for (int mi = 0; mi < 4; mi++)
                #pragma unroll
                for (int ni = 0; ni < 4; ni++) {
                    MMA_TF32(acc[mi][ni], a4[mi],
                             __float_as_uint(b4[ni].x), __float_as_uint(b4[ni].y));
                    MMA_TF32(acc[mi][ni], a4[mi],
                             __float_as_uint(b4[ni].z), __float_as_uint(b4[ni].w));
                }
        }
    }

    // ---- epilogue: bias + relu, float2 stores ----
    #pragma unroll
    for (int ni = 0; ni < 4; ni++) {
        int cc = wn0 + ni * 8 + 2 * tg;
        float b0 = bias[cc], b1 = bias[cc + 1];
        #pragma unroll
        for (int mi = 0; mi < 4; mi++) {
            int r1 = tile0 + h * 64 + mi * 16 + g;
            if (r1 < NN) {
                float2 o;
                o.x = fmaxf(acc[mi][ni][0] + b0, 0.f);
                o.y = fmaxf(acc[mi][ni][1] + b1, 0.f);
                *(float2*)&xout[(size_t)r1 * M + cc] = o;
            }
            int r2 = r1 + 8;
            if (r2 < NN) {
                float2 o;
                o.x = fmaxf(acc[mi][ni][2] + b0, 0.f);
                o.y = fmaxf(acc[mi][ni][3] + b1, 0.f);
                *(float2*)&xout[(size_t)r2 * M + cc] = o;
            }
        }
    }
}

// ---------------------------------------------------------------------------
// Fused mean-pool + 3-layer MLP regressor (reads g_bufA after layer 2).
// ---------------------------------------------------------------------------
__global__ void pool_mlp_kernel(
    const float* __restrict__ rW1, const float* __restrict__ rb1,
    const float* __restrict__ rW2, const float* __restrict__ rb2,
    const float* __restrict__ rW3, const float* __restrict__ rb3,
    float* __restrict__ out)
{
    __shared__ float p[M];
    __shared__ float h1[64];
    __shared__ float h2[32];
    int g = blockIdx.x, t = threadIdx.x;

    const float* base = g_bufA + (size_t)g * NPG * M;
    float s = 0.f;
    for (int i = 0; i < NPG; i++) s += base[(size_t)i * M + t];
    p[t] = s / (float)NPG;
    __syncthreads();

    if (t < 64) {
        float a = rb1[t];
        for (int k = 0; k < M; k++) a = fmaf(p[k], rW1[k * 64 + t], a);
        h1[t] = fmaxf(a, 0.f);
    }
    __syncthreads();
    if (t < 32) {
        float a = rb2[t];
        for (int k = 0; k < 64; k++) a = fmaf(h1[k], rW2[k * 32 + t], a);
        h2[t] = fmaxf(a, 0.f);
    }
    __syncthreads();
    if (t < 32) {
        float a = h2[t] * rW3[t];
        #pragma unroll
        for (int off = 16; off; off >>= 1) a += __shfl_down_sync(0xffffffffu, a, off);
        if (t == 0) out[g] = a + rb3[0];
    }
}

// ---------------------------------------------------------------------------
// kernel_launch: ONLY kernel launches (proven capture-safe path).
// ---------------------------------------------------------------------------
extern "C" void kernel_launch(void* const* d_in, const int* in_sizes, int n_in,
                              void* d_out, int out_size)
{
    const int*   z     = (const int*)  d_in[0];
    const float* pos   = (const float*)d_in[1];
    // d_in[2] = batch (uniform: node i -> graph i/200) — unused
    const float* emb   = (const float*)d_in[3];
    const float* convW = (const float*)d_in[4];
    const float* convb = (const float*)d_in[5];
    const float* rW1   = (const float*)d_in[6];
    const float* rb1   = (const float*)d_in[7];
    const float* rW2   = (const float*)d_in[8];
    const float* rb2   = (const float*)d_in[9];
    const float* rW3   = (const float*)d_in[10];
    const float* rb3   = (const float*)d_in[11];
    float* out = (float*)d_out;

    knn_kernel<<<Gnum, 256>>>(pos);

    int ntiles = (NN + 127) / 128;
    gcn_layer_kernel<<<ntiles, 256>>>(z, emb, convW + 0 * M * M, convb + 0 * M, 0);
    gcn_layer_kernel<<<ntiles, 256>>>(z, emb, convW + 1 * M * M, convb + 1 * M, 1);
    gcn_layer_kernel<<<ntiles, 256>>>(z, emb, convW + 2 * M * M, convb + 2 * M, 2);

    pool_mlp_kernel<<<Gnum, 128>>>(rW1, rb1, rW2, rb2, rW3, rb3, out);
}

// round 8
// speedup vs baseline: 1.4807x; 1.0001x over previous
#include <cuda_runtime.h>

#define Gnum 1000
#define NPG  200
#define NN   200000
#define KNB  5
#define M    128
#define CH   32       // K per smem stage (4 mma k-steps)
#define NCHK (M / CH) // 4 chunks

// Scratch (no allocation allowed): neighbor lists + ping-pong feature buffers.
__device__ int   g_nbr[NN * KNB];
__device__ float g_bufA[(size_t)NN * M];
__device__ float g_bufB[(size_t)NN * M];

// ---------------------------------------------------------------------------
// tf32 helpers
// ---------------------------------------------------------------------------
__device__ __forceinline__ float f2tf(float x) {
    unsigned r;
    asm("cvt.rna.tf32.f32 %0, %1;" : "=r"(r) : "f"(x));
    return __uint_as_float(r);
}

#define MMA_TF32(d, a, b0, b1)                                                \
    asm volatile(                                                             \
        "mma.sync.aligned.m16n8k8.row.col.f32.tf32.tf32.f32 "                 \
        "{%0,%1,%2,%3},{%4,%5,%6,%7},{%8,%9},{%0,%1,%2,%3};"                  \
        : "+f"(d[0]), "+f"(d[1]), "+f"(d[2]), "+f"(d[3])                      \
        : "r"(a.x), "r"(a.y), "r"(a.z), "r"(a.w), "r"(b0), "r"(b1))

// ---------------------------------------------------------------------------
// KNN: one block per graph (unchanged — proven correct).
// ---------------------------------------------------------------------------
__global__ void knn_kernel(const float* __restrict__ pos) {
    __shared__ float px[NPG], py[NPG], pz[NPG];
    int g = blockIdx.x;
    int t = threadIdx.x;
    if (t < NPG) {
        const float* p = pos + (size_t)(g * NPG + t) * 3;
        px[t] = p[0]; py[t] = p[1]; pz[t] = p[2];
    }
    __syncthreads();
    if (t >= NPG) return;

    float bd0 = 3.4e38f, bd1 = 3.4e38f, bd2 = 3.4e38f, bd3 = 3.4e38f, bd4 = 3.4e38f;
    int   bi0 = 0, bi1 = 0, bi2 = 0, bi3 = 0, bi4 = 0;
    float x0 = px[t], y0 = py[t], z0 = pz[t];

    for (int j = 0; j < NPG; j++) {
        if (j == t) continue;
        float dx = __fadd_rn(x0, -px[j]);
        float dy = __fadd_rn(y0, -py[j]);
        float dz = __fadd_rn(z0, -pz[j]);
        float d2 = __fadd_rn(__fadd_rn(__fmul_rn(dx, dx), __fmul_rn(dy, dy)),
                             __fmul_rn(dz, dz));
        if (d2 < bd4) {
            if (d2 < bd3) { bd4 = bd3; bi4 = bi3;
                if (d2 < bd2) { bd3 = bd2; bi3 = bi2;
                    if (d2 < bd1) { bd2 = bd1; bi2 = bi1;
                        if (d2 < bd0) { bd1 = bd0; bi1 = bi0; bd0 = d2; bi0 = j; }
                        else         { bd1 = d2; bi1 = j; }
                    } else { bd2 = d2; bi2 = j; }
                } else { bd3 = d2; bi3 = j; }
            } else { bd4 = d2; bi4 = j; }
        }
    }
    int base = (g * NPG + t) * KNB;
    int off  = g * NPG;
    g_nbr[base + 0] = off + bi0;
    g_nbr[base + 1] = off + bi1;
    g_nbr[base + 2] = off + bi2;
    g_nbr[base + 3] = off + bi3;
    g_nbr[base + 4] = off + bi4;
}

// ---------------------------------------------------------------------------
// Fused GCN layer, tensor-core + fragment-layout smem edition.
//   s[i] = (x[i] + sum_knn x[j]) / 6 ;  x' = relu(s @ W + b)
//   s in tf32, W split hi+lo tf32 (compensated), fp32 accum.
//
// Block: 128 rows x 128 cols, 8 warps = 2(m-half) x 4(n), warp 64x32,
// mma m16n8k8. K chunked by 32.
//  - Gather: 8 threads/row (16B each) -> warp-wide LDG touches only 4 lines.
//  - A chunk stored DIRECTLY in mma fragment layout -> 1 LDS.128 per a-frag.
//  - W chunk packed float4 {hi(k),hi(k+4),lo(k),lo(k+4)} with XOR(2*tg)
//    swizzle -> 1 conflict-free LDS.128 yields both hi and lo b-frags.
// mode: 0 = emb[z] -> bufA, 1 = bufA -> bufB, 2 = bufB -> bufA.
// ---------------------------------------------------------------------------
__global__ void __launch_bounds__(256, 2) gcn_layer_kernel(
    const int*   __restrict__ z,
    const float* __restrict__ emb,
    const float* __restrict__ W,
    const float* __restrict__ bias,
    int mode)
{
    // A frag chunk: [h][ks][mi][g][tg] float4-slots, slot = pos_row + 2*pos_hi
    __shared__ float  sAf[2 * 4 * 4 * 8 * 4 * 4];   // 16384 B
    // W packed chunk: [ks][tg][n^ (2*tg)] float4 {hi_k, hi_k4, lo_k, lo_k4}
    __shared__ float4 sWf[4 * 4 * 128];             // 32768 B   (total 48 KB)

    const float* xin  = (mode == 1) ? g_bufA : g_bufB;
    float*       xout = (mode == 1) ? g_bufB : g_bufA;
    const float* gbase = (mode == 0) ? emb : xin;

    int t     = threadIdx.x;
    int tile0 = blockIdx.x * 128;

    // ---- gather role: thread owns 16B (4 floats) of one row per pass ----
    int sub   = t & 7;        // which 16B segment of the 128B chunk-row
    int rbase = t >> 3;       // 0..31, row within pass
    int ksg   = sub >> 1;     // ks of my 4 floats
    int poshi = sub & 1;      // tg+4 half?

    unsigned offs[4][6];
    bool val[4];
    #pragma unroll
    for (int p = 0; p < 4; p++) {
        int r = p * 32 + rbase;
        int i = tile0 + r;
        val[p] = (i < NN);
        if (val[p]) {
            if (mode == 0) {
                offs[p][0] = (unsigned)z[i] * M;
                #pragma unroll
                for (int j = 0; j < KNB; j++)
                    offs[p][1 + j] = (unsigned)z[g_nbr[i * KNB + j]] * M;
            } else {
                offs[p][0] = (unsigned)i * M;
                #pragma unroll
                for (int j = 0; j < KNB; j++)
                    offs[p][1 + j] = (unsigned)g_nbr[i * KNB + j] * M;
            }
        } else {
            #pragma unroll
            for (int j = 0; j < 6; j++) offs[p][j] = 0;
        }
    }

    // ---- W staging role: thread -> (wks, wtg, 8 consecutive n) ----
    int wks = t >> 6;            // 0..3
    int wtg = (t >> 4) & 3;      // 0..3
    int wn  = (t & 15) * 8;      // 0..120

    // ---- mma role ----
    int lane = t & 31, wid = t >> 5;
    int g  = lane >> 2, tg = lane & 3;
    int h  = wid >> 2;                 // m-half (rows h*64 ..)
    int wn0 = (wid & 3) * 32;          // warp col base

    float acc[4][4][4];
    #pragma unroll
    for (int mi = 0; mi < 4; mi++)
        #pragma unroll
        for (int ni = 0; ni < 4; ni++)
            #pragma unroll
            for (int q = 0; q < 4; q++) acc[mi][ni][q] = 0.f;

    for (int c = 0; c < NCHK; c++) {
        if (c) __syncthreads();

        // ---- stage W chunk: 4 coalesced LDG.128, convert, 8 STS.128 ----
        {
            const float* w0 = W + (size_t)(c * CH + wks * 8 + wtg) * M + wn;
            const float* w1 = w0 + 4 * M;
            float4 A0 = *(const float4*)w0;
            float4 A1 = *(const float4*)(w0 + 4);
            float4 B0 = *(const float4*)w1;
            float4 B1 = *(const float4*)(w1 + 4);
            float wa[8] = {A0.x, A0.y, A0.z, A0.w, A1.x, A1.y, A1.z, A1.w};
            float wb[8] = {B0.x, B0.y, B0.z, B0.w, B1.x, B1.y, B1.z, B1.w};
            float4* dstrow = &sWf[(wks * 4 + wtg) * 128];
            int xr = 2 * wtg;
            #pragma unroll
            for (int i2 = 0; i2 < 8; i2++) {
                float ha = f2tf(wa[i2]);
                float la = f2tf(wa[i2] - ha);
                float hb = f2tf(wb[i2]);
                float lb = f2tf(wb[i2] - hb);
                dstrow[(wn + i2) ^ xr] = make_float4(ha, hb, la, lb);
            }
        }

        // ---- gather + scatter into A fragment layout ----
        #pragma unroll
        for (int p = 0; p < 4; p++) {
            int r = p * 32 + rbase;
            float v0 = 0.f, v1 = 0.f, v2 = 0.f, v3 = 0.f;
            if (val[p]) {
                int kg = c * CH + sub * 4;
                const float* pr = gbase + offs[p][0] + kg;
                float4 a = *(const float4*)pr;
                #pragma unroll
                for (int j = 1; j < 6; j++) {
                    float4 u = *(const float4*)(gbase + offs[p][j] + kg);
                    a.x += u.x; a.y += u.y; a.z += u.z; a.w += u.w;
                }
                const float wnm = 1.0f / 6.0f;
                v0 = f2tf(a.x * wnm); v1 = f2tf(a.y * wnm);
                v2 = f2tf(a.z * wnm); v3 = f2tf(a.w * wnm);
            }
            int hh = r >> 6, mi = (r >> 4) & 3, gg = r & 7, posr = (r >> 3) & 1;
            int s = posr + 2 * poshi;
            int fb = ((((hh * 4 + ksg) * 4 + mi) * 8 + gg) * 4) * 4 + s;
            sAf[fb +  0] = v0;
            sAf[fb +  4] = v1;
            sAf[fb +  8] = v2;
            sAf[fb + 12] = v3;
        }
        __syncthreads();

        // ---- MMA over chunk: 4 k-steps ----
        #pragma unroll
        for (int ks = 0; ks < 4; ks++) {
            uint4 a4[4];
            #pragma unroll
            for (int mi = 0; mi < 4; mi++) {
                int fidx = (((h * 4 + ks) * 4 + mi) * 8 + g) * 4 + tg;
                a4[mi] = *(const uint4*)&sAf[fidx * 4];
            }
            float4 b4[4];
            #pragma unroll
            for (int ni = 0; ni < 4; ni++) {
                int n = wn0 + ni * 8 + g;
                b4[ni] = sWf[(ks * 4 + tg) * 128 + (n ^ (2 * tg))];
            }
            #pragma unroll
            for (int mi = 0; mi < 4; mi++)
                #pragma unroll
                for (int ni = 0; ni < 4; ni++) {
                    MMA_TF32(acc[mi][ni], a4[mi],
                             __float_as_uint(b4[ni].x), __float_as_uint(b4[ni].y));
                    MMA_TF32(acc[mi][ni], a4[mi],
                             __float_as_uint(b4[ni].z), __float_as_uint(b4[ni].w));
                }
        }
    }

    // ---- epilogue: bias + relu, float2 stores ----
    #pragma unroll
    for (int ni = 0; ni < 4; ni++) {
        int cc = wn0 + ni * 8 + 2 * tg;
        float b0 = bias[cc], b1 = bias[cc + 1];
        #pragma unroll
        for (int mi = 0; mi < 4; mi++) {
            int r1 = tile0 + h * 64 + mi * 16 + g;
            if (r1 < NN) {
                float2 o;
                o.x = fmaxf(acc[mi][ni][0] + b0, 0.f);
                o.y = fmaxf(acc[mi][ni][1] + b1, 0.f);
                *(float2*)&xout[(size_t)r1 * M + cc] = o;
            }
            int r2 = r1 + 8;
            if (r2 < NN) {
                float2 o;
                o.x = fmaxf(acc[mi][ni][2] + b0, 0.f);
                o.y = fmaxf(acc[mi][ni][3] + b1, 0.f);
                *(float2*)&xout[(size_t)r2 * M + cc] = o;
            }
        }
    }
}

// ---------------------------------------------------------------------------
// Fused mean-pool + 3-layer MLP regressor (reads g_bufA after layer 2).
// ---------------------------------------------------------------------------
__global__ void pool_mlp_kernel(
    const float* __restrict__ rW1, const float* __restrict__ rb1,
    const float* __restrict__ rW2, const float* __restrict__ rb2,
    const float* __restrict__ rW3, const float* __restrict__ rb3,
    float* __restrict__ out)
{
    __shared__ float p[M];
    __shared__ float h1[64];
    __shared__ float h2[32];
    int g = blockIdx.x, t = threadIdx.x;

    const float* base = g_bufA + (size_t)g * NPG * M;
    float s = 0.f;
    for (int i = 0; i < NPG; i++) s += base[(size_t)i * M + t];
    p[t] = s / (float)NPG;
    __syncthreads();

    if (t < 64) {
        float a = rb1[t];
        for (int k = 0; k < M; k++) a = fmaf(p[k], rW1[k * 64 + t], a);
        h1[t] = fmaxf(a, 0.f);
    }
    __syncthreads();
    if (t < 32) {
        float a = rb2[t];
        for (int k = 0; k < 64; k++) a = fmaf(h1[k], rW2[k * 32 + t], a);
        h2[t] = fmaxf(a, 0.f);
    }
    __syncthreads();
    if (t < 32) {
        float a = h2[t] * rW3[t];
        #pragma unroll
        for (int off = 16; off; off >>= 1) a += __shfl_down_sync(0xffffffffu, a, off);
        if (t == 0) out[g] = a + rb3[0];
    }
}

// ---------------------------------------------------------------------------
// kernel_launch: ONLY kernel launches (proven capture-safe path).
// ---------------------------------------------------------------------------
extern "C" void kernel_launch(void* const* d_in, const int* in_sizes, int n_in,
                              void* d_out, int out_size)
{
    const int*   z     = (const int*)  d_in[0];
    const float* pos   = (const float*)d_in[1];
    // d_in[2] = batch (uniform: node i -> graph i/200) — unused
    const float* emb   = (const float*)d_in[3];
    const float* convW = (const float*)d_in[4];
    const float* convb = (const float*)d_in[5];
    const float* rW1   = (const float*)d_in[6];
    const float* rb1   = (const float*)d_in[7];
    const float* rW2   = (const float*)d_in[8];
    const float* rb2   = (const float*)d_in[9];
    const float* rW3   = (const float*)d_in[10];
    const float* rb3   = (const float*)d_in[11];
    float* out = (float*)d_out;

    knn_kernel<<<Gnum, 256>>>(pos);

    int ntiles = (NN + 127) / 128;
    gcn_layer_kernel<<<ntiles, 256>>>(z, emb, convW + 0 * M * M, convb + 0 * M, 0);
    gcn_layer_kernel<<<ntiles, 256>>>(z, emb, convW + 1 * M * M, convb + 1 * M, 1);
    gcn_layer_kernel<<<ntiles, 256>>>(z, emb, convW + 2 * M * M, convb + 2 * M, 2);

    pool_mlp_kernel<<<Gnum, 128>>>(rW1, rb1, rW2, rb2, rW3, rb3, out);
}

// round 12
// speedup vs baseline: 2.7351x; 1.8472x over previous
#include <cuda_runtime.h>
#include <cuda_fp16.h>
#include <cstdint>

#define Gnum 1000
#define NPG  200
#define NN   200000
#define KNB  5
#define M    128
#define SRU  68      // sA row stride in u32 (136 halves = 272B, odd 16B units)

// Scratch: neighbor lists, f16 ping-pong features, frag-ordered W image.
__device__ int    g_nbr[NN * KNB];
__device__ __half g_bufA[(size_t)NN * M];
__device__ __half g_bufB[(size_t)NN * M];
// W image: [layer][ng][ks][lane] uint4 = {b0_hi, b1_hi, b0_lo, b1_lo}
__device__ uint4  g_wimg[3 * 16 * 8 * 32];

__device__ __forceinline__ uint32_t pkh2(float a, float b) {
    __half2 h = __floats2half2_rn(a, b);     // low half = a (lower col)
    return *(uint32_t*)&h;
}

// m16n8k16 f16 mma, fp32 accumulate (row.col). Frag maps are the k16
// generalization of the tf32 k8 pattern proven in R6-R8.
#define MMA_F16(d, A0, A1, A2, A3, B0, B1)                                    \
    asm volatile(                                                             \
        "mma.sync.aligned.m16n8k16.row.col.f32.f16.f16.f32 "                  \
        "{%0,%1,%2,%3},{%4,%5,%6,%7},{%8,%9},{%0,%1,%2,%3};"                  \
        : "+f"(d[0]), "+f"(d[1]), "+f"(d[2]), "+f"(d[3])                      \
        : "r"(A0), "r"(A1), "r"(A2), "r"(A3), "r"(B0), "r"(B1))

// ---------------------------------------------------------------------------
// KNN: one block per graph (unchanged — proven correct).
// ---------------------------------------------------------------------------
__global__ void knn_kernel(const float* __restrict__ pos) {
    __shared__ float px[NPG], py[NPG], pz[NPG];
    int g = blockIdx.x, t = threadIdx.x;
    if (t < NPG) {
        const float* p = pos + (size_t)(g * NPG + t) * 3;
        px[t] = p[0]; py[t] = p[1]; pz[t] = p[2];
    }
    __syncthreads();
    if (t >= NPG) return;
    float bd0 = 3.4e38f, bd1 = 3.4e38f, bd2 = 3.4e38f, bd3 = 3.4e38f, bd4 = 3.4e38f;
    int   bi0 = 0, bi1 = 0, bi2 = 0, bi3 = 0, bi4 = 0;
    float x0 = px[t], y0 = py[t], z0 = pz[t];
    for (int j = 0; j < NPG; j++) {
        if (j == t) continue;
        float dx = __fadd_rn(x0, -px[j]);
        float dy = __fadd_rn(y0, -py[j]);
        float dz = __fadd_rn(z0, -pz[j]);
        float d2 = __fadd_rn(__fadd_rn(__fmul_rn(dx, dx), __fmul_rn(dy, dy)),
                             __fmul_rn(dz, dz));
        if (d2 < bd4) {
            if (d2 < bd3) { bd4 = bd3; bi4 = bi3;
                if (d2 < bd2) { bd3 = bd2; bi3 = bi2;
                    if (d2 < bd1) { bd2 = bd1; bi2 = bi1;
                        if (d2 < bd0) { bd1 = bd0; bi1 = bi0; bd0 = d2; bi0 = j; }
                        else         { bd1 = d2; bi1 = j; }
                    } else { bd2 = d2; bi2 = j; }
                } else { bd3 = d2; bi3 = j; }
            } else { bd4 = d2; bi4 = j; }
        }
    }
    int base = (g * NPG + t) * KNB, off = g * NPG;
    g_nbr[base + 0] = off + bi0; g_nbr[base + 1] = off + bi1;
    g_nbr[base + 2] = off + bi2; g_nbr[base + 3] = off + bi3;
    g_nbr[base + 4] = off + bi4;
}

// ---------------------------------------------------------------------------
// W prep: bake the b-fragments for every (layer, n-group, kstep, lane) into a
// frag-ordered image so the GEMM reads b-frags with ONE coalesced LDG.128.
// b0 = {W[k0][n], W[k0+1][n]}, b1 = {W[k0+8][n], W[k0+9][n]}, k0 = 16ks + 2tg,
// n = ng*8 + g  (lane = g*4 + tg).  hi = f16(w), lo = f16(w - hi).
// ---------------------------------------------------------------------------
__global__ void wprep_kernel(const float* __restrict__ convW) {
    int idx = blockIdx.x * blockDim.x + threadIdx.x;
    if (idx >= 3 * 16 * 8 * 32) return;
    int lane = idx & 31;
    int ks   = (idx >> 5) & 7;
    int ng   = (idx >> 8) & 15;
    int l    = idx >> 12;
    int g = lane >> 2, tg = lane & 3;
    int n  = ng * 8 + g;
    int k0 = ks * 16 + 2 * tg;
    const float* Wb = convW + (size_t)l * M * M;
    float w00 = Wb[(size_t)(k0    ) * M + n];
    float w01 = Wb[(size_t)(k0 + 1) * M + n];
    float w10 = Wb[(size_t)(k0 + 8) * M + n];
    float w11 = Wb[(size_t)(k0 + 9) * M + n];
    __half h00 = __float2half_rn(w00), h01 = __float2half_rn(w01);
    __half h10 = __float2half_rn(w10), h11 = __float2half_rn(w11);
    float  l00 = w00 - __half2float(h00), l01 = w01 - __half2float(h01);
    float  l10 = w10 - __half2float(h10), l11 = w11 - __half2float(h11);
    uint4 v;
    {
        __half2 a = __halves2half2(h00, h01); v.x = *(uint32_t*)&a;
        __half2 b = __halves2half2(h10, h11); v.y = *(uint32_t*)&b;
    }
    v.z = pkh2(l00, l01);
    v.w = pkh2(l10, l11);
    g_wimg[idx] = v;
}

// ---------------------------------------------------------------------------
// Fused GCN layer (mma.sync f16 edition).
//   s[i] = (x[i] + sum_knn x[j]) / 6 ;  x' = relu(s @ W + b)
//   x stored f16 (same 11-bit mantissa as R6's tf32 path), A single f16,
//   W compensated hi+lo f16 (2 MMA products), fp32 accumulation.
// Block: 128 rows x 128 cols, 8 warps = 2(m) x 4(n), warp 64x32.
// Whole K=128 A tile staged once (34KB smem) -> single sync phase.
// b-frags read straight from the L1-resident W image (no W smem at all).
// Epilogue: f16 pack -> smem transpose -> coalesced uint4 stores.
// mode/layer: 0 = emb[z] -> bufA, 1 = bufA -> bufB, 2 = bufB -> bufA.
// ---------------------------------------------------------------------------
__global__ void __launch_bounds__(256, 2) gcn_layer_kernel(
    const int*   __restrict__ z,
    const float* __restrict__ emb,
    const float* __restrict__ bias,
    int mode)
{
    __shared__ __align__(16) uint32_t sAu[128 * SRU];   // 34816 B (A tile / epi)
    __shared__ float sbias[M];

    const __half* xin  = (mode == 1) ? g_bufA : g_bufB;
    __half*       xout = (mode == 1) ? g_bufB : g_bufA;

    int t = threadIdx.x, lane = t & 31, wid = t >> 5;
    int tile0 = blockIdx.x * 128;
    if (t < M) sbias[t] = bias[t];

    // ---- gather + aggregate + f16 pack + STS (8 threads/row, 4 passes) ----
    int seg = t & 7, rbase = t >> 3;
    const float inv6 = 1.0f / 6.0f;
    #pragma unroll
    for (int p = 0; p < 4; p++) {
        int r = p * 32 + rbase, i = tile0 + r;
        float s[16];
        #pragma unroll
        for (int q = 0; q < 16; q++) s[q] = 0.f;
        if (i < NN) {
            unsigned o[6];
            if (mode == 0) {
                o[0] = (unsigned)z[i] * M;
                #pragma unroll
                for (int j = 0; j < KNB; j++)
                    o[1 + j] = (unsigned)z[g_nbr[i * KNB + j]] * M;
                #pragma unroll
                for (int j = 0; j < 6; j++) {
                    const float4* pr = (const float4*)(emb + o[j] + seg * 16);
                    float4 u0 = pr[0], u1 = pr[1], u2 = pr[2], u3 = pr[3];
                    s[0]  += u0.x; s[1]  += u0.y; s[2]  += u0.z; s[3]  += u0.w;
                    s[4]  += u1.x; s[5]  += u1.y; s[6]  += u1.z; s[7]  += u1.w;
                    s[8]  += u2.x; s[9]  += u2.y; s[10] += u2.z; s[11] += u2.w;
                    s[12] += u3.x; s[13] += u3.y; s[14] += u3.z; s[15] += u3.w;
                }
            } else {
                o[0] = (unsigned)i * M;
                #pragma unroll
                for (int j = 0; j < KNB; j++)
                    o[1 + j] = (unsigned)g_nbr[i * KNB + j] * M;
                #pragma unroll
                for (int j = 0; j < 6; j++) {
                    const uint4* pr = (const uint4*)(xin + o[j] + seg * 16);
                    uint4 u0 = pr[0], u1 = pr[1];
                    const __half2* ha = (const __half2*)&u0;
                    const __half2* hb = (const __half2*)&u1;
                    #pragma unroll
                    for (int q = 0; q < 4; q++) {
                        float2 fa = __half22float2(ha[q]);
                        float2 fb = __half22float2(hb[q]);
                        s[2 * q]     += fa.x; s[2 * q + 1] += fa.y;
                        s[8 + 2 * q] += fb.x; s[8 + 2 * q + 1] += fb.y;
                    }
                }
            }
        }
        uint32_t pk[8];
        #pragma unroll
        for (int q = 0; q < 8; q++)
            pk[q] = pkh2(s[2 * q] * inv6, s[2 * q + 1] * inv6);
        uint32_t* dst = sAu + r * SRU + seg * 8;
        *(uint4*)(dst)     = make_uint4(pk[0], pk[1], pk[2], pk[3]);
        *(uint4*)(dst + 4) = make_uint4(pk[4], pk[5], pk[6], pk[7]);
    }
    __syncthreads();

    // ---- MMA: 8 ksteps of k16, 4x4 tiles/warp, hi+lo W products ----
    int g = lane >> 2, tg = lane & 3;
    int wm0 = (wid >> 2) * 64, wn0 = (wid & 3) * 32;
    float acc[4][4][4];
    #pragma unroll
    for (int mi = 0; mi < 4; mi++)
        #pragma unroll
        for (int ni = 0; ni < 4; ni++)
            #pragma unroll
            for (int q = 0; q < 4; q++) acc[mi][ni][q] = 0.f;

    const uint4* img = g_wimg + mode * 4096;
    int nb = wn0 >> 3;
    #pragma unroll
    for (int ks = 0; ks < 8; ks++) {
        uint4 bf[4];
        #pragma unroll
        for (int ni = 0; ni < 4; ni++)
            bf[ni] = img[((nb + ni) * 8 + ks) * 32 + lane];
        uint32_t a0[4], a1[4], a2[4], a3[4];
        #pragma unroll
        for (int mi = 0; mi < 4; mi++) {
            const uint32_t* rp = sAu + (wm0 + mi * 16 + g) * SRU + 8 * ks + tg;
            const uint32_t* rq = rp + 8 * SRU;
            a0[mi] = rp[0]; a2[mi] = rp[4];
            a1[mi] = rq[0]; a3[mi] = rq[4];
        }
        #pragma unroll
        for (int mi = 0; mi < 4; mi++)
            #pragma unroll
            for (int ni = 0; ni < 4; ni++) {
                MMA_F16(acc[mi][ni], a0[mi], a1[mi], a2[mi], a3[mi],
                        bf[ni].x, bf[ni].y);
                MMA_F16(acc[mi][ni], a0[mi], a1[mi], a2[mi], a3[mi],
                        bf[ni].z, bf[ni].w);
            }
    }
    __syncthreads();   // A tile consumed; reuse smem for epilogue

    // ---- epilogue: bias+relu, f16 pack, smem transpose (conflict-free) ----
    #pragma unroll
    for (int ni = 0; ni < 4; ni++) {
        int c0 = wn0 + ni * 8 + 2 * tg;
        float b0 = sbias[c0], b1 = sbias[c0 + 1];
        int colu = (wn0 >> 1) + ni * 4 + tg;
        #pragma unroll
        for (int mi = 0; mi < 4; mi++) {
            int row = wm0 + mi * 16 + g;
            sAu[row * SRU + colu] =
                pkh2(fmaxf(acc[mi][ni][0] + b0, 0.f),
                     fmaxf(acc[mi][ni][1] + b1, 0.f));
            sAu[(row + 8) * SRU + colu] =
                pkh2(fmaxf(acc[mi][ni][2] + b0, 0.f),
                     fmaxf(acc[mi][ni][3] + b1, 0.f));
        }
    }
    __syncthreads();

    // ---- coalesced f16 stores: 128 rows x 256B via uint4 ----
    #pragma unroll
    for (int it = 0; it < 8; it++) {
        int flat = it * 256 + t;
        int row = flat >> 4, sg = flat & 15;
        int grow = tile0 + row;
        if (grow < NN)
            *(uint4*)(xout + (size_t)grow * M + sg * 8) =
                *(const uint4*)(sAu + row * SRU + sg * 4);
    }
}

// ---------------------------------------------------------------------------
// Fused mean-pool + 3-layer MLP regressor (reads f16 g_bufA after layer 2).
// ---------------------------------------------------------------------------
__global__ void pool_mlp_kernel(
    const float* __restrict__ rW1, const float* __restrict__ rb1,
    const float* __restrict__ rW2, const float* __restrict__ rb2,
    const float* __restrict__ rW3, const float* __restrict__ rb3,
    float* __restrict__ out)
{
    __shared__ float p[M];
    __shared__ float h1[64];
    __shared__ float h2s[32];
    int g = blockIdx.x, t = threadIdx.x;
    const __half* base = g_bufA + (size_t)g * NPG * M;
    float s = 0.f;
    for (int i = 0; i < NPG; i++) s += __half2float(base[(size_t)i * M + t]);
    p[t] = s / (float)NPG;
    __syncthreads();
    if (t < 64) {
        float a = rb1[t];
        for (int k = 0; k < M; k++) a = fmaf(p[k], rW1[k * 64 + t], a);
        h1[t] = fmaxf(a, 0.f);
    }
    __syncthreads();
    if (t < 32) {
        float a = rb2[t];
        for (int k = 0; k < 64; k++) a = fmaf(h1[k], rW2[k * 32 + t], a);
        h2s[t] = fmaxf(a, 0.f);
    }
    __syncthreads();
    if (t < 32) {
        float a = h2s[t] * rW3[t];
        #pragma unroll
        for (int off = 16; off; off >>= 1) a += __shfl_down_sync(0xffffffffu, a, off);
        if (t == 0) out[g] = a + rb3[0];
    }
}

// ---------------------------------------------------------------------------
// kernel_launch: ONLY kernel launches (proven capture-safe path).
// ---------------------------------------------------------------------------
extern "C" void kernel_launch(void* const* d_in, const int* in_sizes, int n_in,
                              void* d_out, int out_size)
{
    const int*   z     = (const int*)  d_in[0];
    const float* pos   = (const float*)d_in[1];
    const float* emb   = (const float*)d_in[3];
    const float* convW = (const float*)d_in[4];
    const float* convb = (const float*)d_in[5];
    const float* rW1   = (const float*)d_in[6];
    const float* rb1   = (const float*)d_in[7];
    const float* rW2   = (const float*)d_in[8];
    const float* rb2   = (const float*)d_in[9];
    const float* rW3   = (const float*)d_in[10];
    const float* rb3   = (const float*)d_in[11];
    float* out = (float*)d_out;

    knn_kernel<<<Gnum, 256>>>(pos);
    wprep_kernel<<<48, 256>>>(convW);

    int ntiles = (NN + 127) / 128;
    gcn_layer_kernel<<<ntiles, 256>>>(z, emb, convb + 0 * M, 0);
    gcn_layer_kernel<<<ntiles, 256>>>(z, emb, convb + 1 * M, 1);
    gcn_layer_kernel<<<ntiles, 256>>>(z, emb, convb + 2 * M, 2);

    pool_mlp_kernel<<<Gnum, 128>>>(rW1, rb1, rW2, rb2, rW3, rb3, out);
}

// round 17
// speedup vs baseline: 3.1042x; 1.1349x over previous
#include <cuda_runtime.h>
#include <cuda_fp16.h>
#include <cstdint>

#define Gnum 1000
#define NPG  200
#define NN   200000
#define KNB  5
#define M    128
#define VOCAB 100
#define SRU  68      // sA row stride in u32 (272B: ldmatrix-conflict-free)

// Scratch: neighbor lists, f16 ping-pong features, W image, f16 emb.
__device__ int    g_nbr[NN * KNB];
__device__ __half g_bufA[(size_t)NN * M];
__device__ __half g_bufB[(size_t)NN * M];
__device__ uint4  g_wimg[3 * 16 * 8 * 32];  // [layer][ng][ks][lane]
__device__ __half g_embh[VOCAB * M];

__device__ __forceinline__ uint32_t pkh2(float a, float b) {
    __half2 h = __floats2half2_rn(a, b);     // low half = a (lower col)
    return *(uint32_t*)&h;
}
__device__ __forceinline__ uint32_t smem_u32(const void* p) {
    uint32_t a;
    asm("{ .reg .u64 t; cvta.to.shared.u64 t, %1; cvt.u32.u64 %0, t; }"
        : "=r"(a) : "l"(p));
    return a;
}

#define MMA_F16(d, A0, A1, A2, A3, B0, B1)                                    \
    asm volatile(                                                             \
        "mma.sync.aligned.m16n8k16.row.col.f32.f16.f16.f32 "                  \
        "{%0,%1,%2,%3},{%4,%5,%6,%7},{%8,%9},{%0,%1,%2,%3};"                  \
        : "+f"(d[0]), "+f"(d[1]), "+f"(d[2]), "+f"(d[3])                      \
        : "r"(A0), "r"(A1), "r"(A2), "r"(A3), "r"(B0), "r"(B1))

#define LDSM_X4(r0, r1, r2, r3, addr)                                         \
    asm volatile("ldmatrix.sync.aligned.m8n8.x4.shared.b16 {%0,%1,%2,%3}, [%4];" \
        : "=r"(r0), "=r"(r1), "=r"(r2), "=r"(r3) : "r"(addr))

// ---------------------------------------------------------------------------
// KNN: one block per graph. float4-packed smem positions (1 LDS.128/candidate).
// Exact __fadd_rn/__fmul_rn arithmetic preserved (tie ordering == reference).
// ---------------------------------------------------------------------------
__global__ void knn_kernel(const float* __restrict__ pos) {
    __shared__ float4 pp[NPG];
    int g = blockIdx.x, t = threadIdx.x;
    if (t < NPG) {
        const float* p = pos + (size_t)(g * NPG + t) * 3;
        pp[t] = make_float4(p[0], p[1], p[2], 0.f);
    }
    __syncthreads();
    if (t >= NPG) return;

    float bd0 = 3.4e38f, bd1 = 3.4e38f, bd2 = 3.4e38f, bd3 = 3.4e38f, bd4 = 3.4e38f;
    int   bi0 = 0, bi1 = 0, bi2 = 0, bi3 = 0, bi4 = 0;
    float4 me = pp[t];

    #pragma unroll 2
    for (int j = 0; j < NPG; j++) {
        float4 q = pp[j];
        float dx = __fadd_rn(me.x, -q.x);
        float dy = __fadd_rn(me.y, -q.y);
        float dz = __fadd_rn(me.z, -q.z);
        float d2 = __fadd_rn(__fadd_rn(__fmul_rn(dx, dx), __fmul_rn(dy, dy)),
                             __fmul_rn(dz, dz));
        if (j == t) continue;
        if (d2 < bd4) {
            if (d2 < bd3) { bd4 = bd3; bi4 = bi3;
                if (d2 < bd2) { bd3 = bd2; bi3 = bi2;
                    if (d2 < bd1) { bd2 = bd1; bi2 = bi1;
                        if (d2 < bd0) { bd1 = bd0; bi1 = bi0; bd0 = d2; bi0 = j; }
                        else         { bd1 = d2; bi1 = j; }
                    } else { bd2 = d2; bi2 = j; }
                } else { bd3 = d2; bi3 = j; }
            } else { bd4 = d2; bi4 = j; }
        }
    }
    int base = (g * NPG + t) * KNB, off = g * NPG;
    g_nbr[base + 0] = off + bi0; g_nbr[base + 1] = off + bi1;
    g_nbr[base + 2] = off + bi2; g_nbr[base + 3] = off + bi3;
    g_nbr[base + 4] = off + bi4;
}

// ---------------------------------------------------------------------------
// Prep: (a) bake b-fragments (hi/lo f16) into frag-ordered W image;
//       (b) convert emb to f16. One kernel, one launch.
// W image idx = [l][ng][ks][lane]; b0={W[k0][n],W[k0+1][n]}, b1={W[k0+8..9][n]},
// k0 = 16ks + 2tg, n = ng*8 + g, lane = g*4+tg. hi=f16(w), lo=f16(w-hi).
// ---------------------------------------------------------------------------
__global__ void prep_kernel(const float* __restrict__ convW,
                            const float* __restrict__ emb) {
    int idx = blockIdx.x * blockDim.x + threadIdx.x;
    if (idx < 3 * 16 * 8 * 32) {
        int lane = idx & 31;
        int ks   = (idx >> 5) & 7;
        int ng   = (idx >> 8) & 15;
        int l    = idx >> 12;
        int g = lane >> 2, tg = lane & 3;
        int n  = ng * 8 + g;
        int k0 = ks * 16 + 2 * tg;
        const float* Wb = convW + (size_t)l * M * M;
        float w00 = Wb[(size_t)(k0    ) * M + n];
        float w01 = Wb[(size_t)(k0 + 1) * M + n];
        float w10 = Wb[(size_t)(k0 + 8) * M + n];
        float w11 = Wb[(size_t)(k0 + 9) * M + n];
        __half h00 = __float2half_rn(w00), h01 = __float2half_rn(w01);
        __half h10 = __float2half_rn(w10), h11 = __float2half_rn(w11);
        uint4 v;
        { __half2 a = __halves2half2(h00, h01); v.x = *(uint32_t*)&a; }
        { __half2 b = __halves2half2(h10, h11); v.y = *(uint32_t*)&b; }
        v.z = pkh2(w00 - __half2float(h00), w01 - __half2float(h01));
        v.w = pkh2(w10 - __half2float(h10), w11 - __half2float(h11));
        g_wimg[idx] = v;
    }
    int e = idx - 3 * 16 * 8 * 32;
    if (e >= 0 && e < VOCAB * M)
        g_embh[e] = __float2half_rn(emb[e]);
}

// ---------------------------------------------------------------------------
// Fused GCN layer (f16 mma.sync, unified f16 gather, ldmatrix a-frags).
//   s[i] = (x[i] + sum_knn x[j]) / 6 ;  x' = relu(s @ W + b)
// Block 128x128, 8 warps = 2(m) x 4(n), warp 64x32, m16n8k16, fp32 acc,
// W compensated hi+lo. Whole K staged once (34KB smem, single sync phase).
// mode: 0 = embh[z] -> bufA, 1 = bufA -> bufB, 2 = bufB -> bufA.
// ---------------------------------------------------------------------------
__global__ void __launch_bounds__(256, 2) gcn_layer_kernel(
    const int*   __restrict__ z,
    const float* __restrict__ bias,
    int mode)
{
    __shared__ __align__(16) uint32_t sAu[128 * SRU];   // 34816 B (A tile / epi)
    __shared__ float sbias[M];

    const __half* xin  = (mode == 1) ? g_bufA : g_bufB;
    __half*       xout = (mode == 1) ? g_bufB : g_bufA;
    const __half* gsrc = (mode == 0) ? g_embh : xin;

    int t = threadIdx.x, lane = t & 31, wid = t >> 5;
    int tile0 = blockIdx.x * 128;
    if (t < M) sbias[t] = bias[t];

    // ---- gather + aggregate + f16 pack + STS (8 threads/row, 4 passes) ----
    int seg = t & 7, rbase = t >> 3;
    const float inv6 = 1.0f / 6.0f;
    #pragma unroll
    for (int p = 0; p < 4; p++) {
        int r = p * 32 + rbase, i = tile0 + r;
        float s[16];
        #pragma unroll
        for (int q = 0; q < 16; q++) s[q] = 0.f;
        if (i < NN) {
            unsigned o[6];
            if (mode == 0) {
                o[0] = (unsigned)z[i] * M;
                #pragma unroll
                for (int j = 0; j < KNB; j++)
                    o[1 + j] = (unsigned)z[g_nbr[i * KNB + j]] * M;
            } else {
                o[0] = (unsigned)i * M;
                #pragma unroll
                for (int j = 0; j < KNB; j++)
                    o[1 + j] = (unsigned)g_nbr[i * KNB + j] * M;
            }
            #pragma unroll
            for (int j = 0; j < 6; j++) {
                const uint4* pr = (const uint4*)(gsrc + o[j] + seg * 16);
                uint4 u0 = pr[0], u1 = pr[1];
                const __half2* ha = (const __half2*)&u0;
                const __half2* hb = (const __half2*)&u1;
                #pragma unroll
                for (int q = 0; q < 4; q++) {
                    float2 fa = __half22float2(ha[q]);
                    float2 fb = __half22float2(hb[q]);
                    s[2 * q]         += fa.x; s[2 * q + 1]     += fa.y;
                    s[8 + 2 * q]     += fb.x; s[8 + 2 * q + 1] += fb.y;
                }
            }
        }
        uint32_t pk[8];
        #pragma unroll
        for (int q = 0; q < 8; q++)
            pk[q] = pkh2(s[2 * q] * inv6, s[2 * q + 1] * inv6);
        uint32_t* dst = sAu + r * SRU + seg * 8;
        *(uint4*)(dst)     = make_uint4(pk[0], pk[1], pk[2], pk[3]);
        *(uint4*)(dst + 4) = make_uint4(pk[4], pk[5], pk[6], pk[7]);
    }
    __syncthreads();

    // ---- MMA: 8 ksteps of k16, ldmatrix a-frags, hi+lo W products ----
    int g = lane >> 2, tg = lane & 3;
    int wm0 = (wid >> 2) * 64, wn0 = (wid & 3) * 32;
    float acc[4][4][4];
    #pragma unroll
    for (int mi = 0; mi < 4; mi++)
        #pragma unroll
        for (int ni = 0; ni < 4; ni++)
            #pragma unroll
            for (int q = 0; q < 4; q++) acc[mi][ni][q] = 0.f;

    // ldmatrix per-lane base: lanes 0-7 -> (rows 0-7, k0-7), 8-15 -> rows+8,
    // 16-23 -> (rows 0-7, k8-15), 24-31 -> (rows+8, k8-15)
    uint32_t sabase = smem_u32(sAu);
    int g8 = lane >> 3, lrow = lane & 7;
    int row_off = (g8 & 1) * 8 + lrow;
    int koff_u32 = (g8 >> 1) * 4;
    uint32_t ld_mi[4];
    #pragma unroll
    for (int mi = 0; mi < 4; mi++)
        ld_mi[mi] = sabase + (uint32_t)(((wm0 + mi * 16 + row_off) * SRU + koff_u32) * 4);

    const uint4* img = g_wimg + mode * 4096;
    int nb = wn0 >> 3;
    #pragma unroll
    for (int ks = 0; ks < 8; ks++) {
        uint4 bf[4];
        #pragma unroll
        for (int ni = 0; ni < 4; ni++)
            bf[ni] = img[((nb + ni) * 8 + ks) * 32 + lane];
        uint32_t a[4][4];
        #pragma unroll
        for (int mi = 0; mi < 4; mi++)
            LDSM_X4(a[mi][0], a[mi][1], a[mi][2], a[mi][3], ld_mi[mi] + ks * 32);
        #pragma unroll
        for (int mi = 0; mi < 4; mi++)
            #pragma unroll
            for (int ni = 0; ni < 4; ni++) {
                MMA_F16(acc[mi][ni], a[mi][0], a[mi][1], a[mi][2], a[mi][3],
                        bf[ni].x, bf[ni].y);
                MMA_F16(acc[mi][ni], a[mi][0], a[mi][1], a[mi][2], a[mi][3],
                        bf[ni].z, bf[ni].w);
            }
    }
    __syncthreads();   // A tile consumed; reuse smem for epilogue

    // ---- epilogue: bias+relu, f16 pack, smem transpose, coalesced stores ----
    #pragma unroll
    for (int ni = 0; ni < 4; ni++) {
        int c0 = wn0 + ni * 8 + 2 * tg;
        float b0 = sbias[c0], b1 = sbias[c0 + 1];
        int colu = (wn0 >> 1) + ni * 4 + tg;
        #pragma unroll
        for (int mi = 0; mi < 4; mi++) {
            int row = wm0 + mi * 16 + g;
            sAu[row * SRU + colu] =
                pkh2(fmaxf(acc[mi][ni][0] + b0, 0.f),
                     fmaxf(acc[mi][ni][1] + b1, 0.f));
            sAu[(row + 8) * SRU + colu] =
                pkh2(fmaxf(acc[mi][ni][2] + b0, 0.f),
                     fmaxf(acc[mi][ni][3] + b1, 0.f));
        }
    }
    __syncthreads();

    #pragma unroll
    for (int it = 0; it < 8; it++) {
        int flat = it * 256 + t;
        int row = flat >> 4, sg = flat & 15;
        int grow = tile0 + row;
        if (grow < NN)
            *(uint4*)(xout + (size_t)grow * M + sg * 8) =
                *(const uint4*)(sAu + row * SRU + sg * 4);
    }
}

// ---------------------------------------------------------------------------
// Fused mean-pool + MLP. 256 threads: row-sum split 2 ways, smem combine.
// ---------------------------------------------------------------------------
__global__ void pool_mlp_kernel(
    const float* __restrict__ rW1, const float* __restrict__ rb1,
    const float* __restrict__ rW2, const float* __restrict__ rb2,
    const float* __restrict__ rW3, const float* __restrict__ rb3,
    float* __restrict__ out)
{
    __shared__ float psum[2][M];
    __shared__ float p[M];
    __shared__ float h1[64];
    __shared__ float h2s[32];
    int g = blockIdx.x, t = threadIdx.x;
    int half = t >> 7, col = t & 127;

    const __half* base = g_bufA + (size_t)g * NPG * M + (size_t)half * 100 * M;
    float s = 0.f;
    #pragma unroll 4
    for (int i = 0; i < 100; i++) s += __half2float(base[(size_t)i * M + col]);
    psum[half][col] = s;
    __syncthreads();
    if (t < M) p[t] = (psum[0][t] + psum[1][t]) / (float)NPG;
    __syncthreads();

    if (t < 64) {
        float a = rb1[t];
        for (int k = 0; k < M; k++) a = fmaf(p[k], rW1[k * 64 + t], a);
        h1[t] = fmaxf(a, 0.f);
    }
    __syncthreads();
    if (t < 32) {
        float a = rb2[t];
        for (int k = 0; k < 64; k++) a = fmaf(h1[k], rW2[k * 32 + t], a);
        h2s[t] = fmaxf(a, 0.f);
    }
    __syncthreads();
    if (t < 32) {
        float a = h2s[t] * rW3[t];
        #pragma unroll
        for (int off = 16; off; off >>= 1) a += __shfl_down_sync(0xffffffffu, a, off);
        if (t == 0) out[g] = a + rb3[0];
    }
}

// ---------------------------------------------------------------------------
// kernel_launch: ONLY kernel launches (proven capture-safe path).
// ---------------------------------------------------------------------------
extern "C" void kernel_launch(void* const* d_in, const int* in_sizes, int n_in,
                              void* d_out, int out_size)
{
    const int*   z     = (const int*)  d_in[0];
    const float* pos   = (const float*)d_in[1];
    const float* emb   = (const float*)d_in[3];
    const float* convW = (const float*)d_in[4];
    const float* convb = (const float*)d_in[5];
    const float* rW1   = (const float*)d_in[6];
    const float* rb1   = (const float*)d_in[7];
    const float* rW2   = (const float*)d_in[8];
    const float* rb2   = (const float*)d_in[9];
    const float* rW3   = (const float*)d_in[10];
    const float* rb3   = (const float*)d_in[11];
    float* out = (float*)d_out;

    knn_kernel<<<Gnum, 256>>>(pos);
    prep_kernel<<<98, 256>>>(convW, emb);   // W image + f16 emb

    int ntiles = (NN + 127) / 128;
    gcn_layer_kernel<<<ntiles, 256>>>(z, convb + 0 * M, 0);
    gcn_layer_kernel<<<ntiles, 256>>>(z, convb + 1 * M, 1);
    gcn_layer_kernel<<<ntiles, 256>>>(z, convb + 2 * M, 2);

    pool_mlp_kernel<<<Gnum, 256>>>(rW1, rb1, rW2, rb2, rW3, rb3, out);
}